// round 8
// baseline (speedup 1.0000x reference)
#include <cuda_runtime.h>
#include <cuda_fp16.h>
#include <math.h>
#include <stdint.h>

#define KNB 40
#define DF 128
#define MDIM 384
#define HH 4
#define DHD 96
#define BB 128
#define R1 409600
#define R2 10240
#define KX 512
#define NOUT 768
#define NPB 8
#define KV2 776              // padded halves per KV row in smem
#define KVBUFH (KNB * KV2)   // 31040 halves per buffer

// ---------------- scratch (__device__ globals, no allocation) ----------------
__device__ __align__(16) __half g_X[(size_t)R1 * KX];          // gathered features (fp16)
__device__ __align__(16) __half g_Wt[2 * NOUT * KX];           // fused K|V weights [l][n][k]
__device__ __align__(16) __half g_KV[(size_t)R1 * NOUT];       // K|V projections (fp16)
__device__ float g_qconst[2][384];
__device__ float g_WoM1[2][384 * 128];
__device__ float g_h1[R2 * DF];
__device__ float g_h2[256 * DF];

// ---------------- helpers ----------------
__device__ __forceinline__ uint32_t smem_u32(const void* p) {
    return (uint32_t)__cvta_generic_to_shared((void*)p);
}
#define CP_ASYNC16(dst, src) \
    asm volatile("cp.async.cg.shared.global [%0], [%1], 16;" :: "r"(dst), "l"(src) : "memory")
#define CP_COMMIT() asm volatile("cp.async.commit_group;" ::: "memory")
#define CP_WAIT(n)  asm volatile("cp.async.wait_group %0;" :: "n"(n) : "memory")
#define LDSM_X4(d0, d1, d2, d3, addr) \
    asm volatile("ldmatrix.sync.aligned.m8n8.x4.shared.b16 {%0,%1,%2,%3}, [%4];" \
        : "=r"(d0), "=r"(d1), "=r"(d2), "=r"(d3) : "r"(addr))

__device__ __forceinline__ void mma16816(float* c, uint32_t a0, uint32_t a1,
                                         uint32_t a2, uint32_t a3,
                                         uint32_t b0, uint32_t b1) {
    asm volatile(
        "mma.sync.aligned.m16n8k16.row.col.f32.f16.f16.f32 "
        "{%0,%1,%2,%3}, {%4,%5,%6,%7}, {%8,%9}, {%0,%1,%2,%3};"
        : "+f"(c[0]), "+f"(c[1]), "+f"(c[2]), "+f"(c[3])
        : "r"(a0), "r"(a1), "r"(a2), "r"(a3), "r"(b0), "r"(b1));
}

// FMA-pipe cos: quadrant range reduction + minimax-style polys on [-pi/4, pi/4].
// Accurate to ~1e-5 for |x| <= ~2000 rad; fp16 downstream makes this exact enough.
__device__ __forceinline__ float fcospoly(float x) {
    float n = rintf(x * 0.6366197723675814f);          // x * 2/pi
    float r = fmaf(n, -1.5707963705062866e0f, x);      // hi of pi/2
    r = fmaf(n, 4.3711388286737929e-8f, r);            // lo correction
    int q = ((int)n) & 3;
    float r2 = r * r;
    float pc = fmaf(r2, fmaf(r2, fmaf(r2, -1.388888889e-3f, 4.166666667e-2f), -0.5f), 1.0f);
    float ps = r * fmaf(r2, fmaf(r2, fmaf(r2, -1.984126984e-4f, 8.333333333e-3f), -1.666666667e-1f), 1.0f);
    float v = (q & 1) ? ps : pc;
    return ((q + 1) & 2) ? -v : v;
}

// ------------- precompute: fused transposed K|V weights (fp16) ---------------
__global__ void pre_weights(const float* __restrict__ Wrel,
                            const float* __restrict__ Wk,
                            const float* __restrict__ Wv) {
    int l = blockIdx.x / NOUT;
    int n = blockIdx.x % NOUT;
    int t = threadIdx.x;   // 128
    const float* Ws = ((n < MDIM) ? Wk : Wv) + (size_t)l * MDIM * MDIM;
    int nc = (n < MDIM) ? n : n - MDIM;
    const float* wr0 = Wrel + ((size_t)(l * 2 + 0) * DF + t) * DF;
    const float* wr1 = Wrel + ((size_t)(l * 2 + 1) * DF + t) * DF;
    float v0 = 0.f, v1 = 0.f;
    for (int j = 0; j < DF; j++) {
        float w = Ws[(size_t)j * MDIM + nc];
        v0 = fmaf(wr0[j], w, v0);
        v1 = fmaf(wr1[j], w, v1);
    }
    size_t base = ((size_t)l * NOUT + n) * KX;
    g_Wt[base + t]        = __float2half_rn(v0);
    g_Wt[base + DF + t]   = __float2half_rn(v1);
    g_Wt[base + 256 + t]  = __float2half_rn(Ws[(size_t)(DF + t) * MDIM + nc]);
    g_Wt[base + 384 + t]  = __float2half_rn(Ws[(size_t)(256 + t) * MDIM + nc]);
}

// ---------------- precompute: qconst + Wo@Wm1 ----------------
__global__ void pre_misc(const float* __restrict__ Wq,
                         const float* __restrict__ Wo,
                         const float* __restrict__ Wm1,
                         const float* __restrict__ phase) {
    int bid = blockIdx.x;          // 770 = 2*(384+1)
    int l = bid / 385;
    int r = bid % 385;
    int tid = threadIdx.x;         // 384
    if (r == 384) {
        float acc = 0.f;
        for (int j = 0; j < 128; j++)
            acc = fmaf(cosf(phase[j]), Wq[(size_t)l * MDIM * MDIM + (256 + j) * MDIM + tid], acc);
        g_qconst[l][tid] = acc;
    } else if (tid < 128) {
        float acc = 0.f;
        for (int j = 0; j < MDIM; j++)
            acc = fmaf(Wo[(size_t)l * MDIM * MDIM + r * MDIM + j],
                       Wm1[(size_t)(l * 512 + j) * 128 + tid], acc);
        g_WoM1[l][r * 128 + tid] = acc;
    }
}

// ---------------- gather: build X rows (fp16), 4 rows per CTA ----------------
__global__ void gather_kernel(int layer, const int* __restrict__ nghNode,
                              const int* __restrict__ nghEidx,
                              const float* __restrict__ nghT,
                              const int* __restrict__ nghEt,
                              const float* __restrict__ parentT,
                              const float* __restrict__ n_feat,
                              const float* __restrict__ mem_tab,
                              const float* __restrict__ e_feat,
                              const float* __restrict__ freq,
                              const float* __restrict__ phase) {
    int r = blockIdx.x * 4 + (threadIdx.x >> 7);
    int j = threadIdx.x & 127;
    int node = nghNode[r];
    int eidx = nghEidx[r];
    int et = nghEt[r];
    int p = r / KNB;
    float tq = (layer == 0) ? parentT[p] : parentT[p & (BB - 1)];
    float dt = tq - nghT[r];
    float nf = (layer == 0)
        ? n_feat[(size_t)node * DF + j] + mem_tab[(size_t)node * DF + j]
        : g_h1[(size_t)r * DF + j];
    float ef = e_feat[(size_t)eidx * DF + j];
    float tf = fcospoly(fmaf(dt, freq[j], phase[j]));
    size_t base = (size_t)r * KX;
    g_X[base + j]        = __float2half_rn((et == 0) ? nf : 0.f);
    g_X[base + DF + j]   = __float2half_rn((et == 1) ? nf : 0.f);
    g_X[base + 256 + j]  = __float2half_rn(ef);
    g_X[base + 384 + j]  = __float2half_rn(tf);
}

// ---------------- HMMA GEMM: KV = X @ Wt' ----------------
// CTA tile 128(M)x256(N), K=512 in 8 chunks of 64, 3-stage cp.async pipeline,
// single barrier per chunk. 8 warps as 2M x 4N, warp tile 64x64.
// Grid: (N-blocks, M-blocks) -> N fastest so X tiles hit L2 across N sweep.
#define STR 72                         // padded smem stride in halves (144B rows)
#define ABYTES (128 * STR * 2)         // 18432
#define BBYTES (256 * STR * 2)         // 36864
#define STAGEB (ABYTES + BBYTES)       // 55296 per stage
__global__ __launch_bounds__(256, 1)
void gemm_kernel(int layer) {
    extern __shared__ char smem[];
    const uint32_t smem_base = smem_u32(smem);
    const int tid = threadIdx.x;
    const int wid = tid >> 5;
    const int lane = tid & 31;
    const int n0 = blockIdx.x * 256;
    const int m0 = blockIdx.y * 128;
    const int mbase = (wid >> 2) * 64;               // 2 M-warps
    const int nbase = (wid & 3) * 64;                // 4 N-warps

    const int lrow = lane & 15;                      // A: row within 16
    const int akh  = (lane >> 4) * 8;                // A: k-half select
    const int brow = (lane & 7) + ((lane >> 4) * 8); // B: row within 16
    const int bkh  = ((lane >> 3) & 1) * 8;          // B: k-half select

    const __half* gW = g_Wt + (size_t)layer * NOUT * KX;

    float acc[4][8][4];
#pragma unroll
    for (int mt = 0; mt < 4; mt++)
#pragma unroll
        for (int nt = 0; nt < 8; nt++)
#pragma unroll
            for (int q = 0; q < 4; q++) acc[mt][nt][q] = 0.f;

    auto stage = [&](int c) {
        const int kb = c * 64;
        const uint32_t sbase = smem_base + (c % 3) * STAGEB;
#pragma unroll
        for (int it = 0; it < 12; it++) {
            int i = tid + it * 256;                // 0..3071
            if (i < 1024) {                        // A: 128 rows x 8 segs
                int row = i >> 3, seg = i & 7;
                CP_ASYNC16(sbase + (uint32_t)(row * STR + seg * 8) * 2,
                           g_X + (size_t)(m0 + row) * KX + kb + seg * 8);
            } else {                               // B: 256 rows x 8 segs
                int j = i - 1024;
                int row = j >> 3, seg = j & 7;
                CP_ASYNC16(sbase + ABYTES + (uint32_t)(row * STR + seg * 8) * 2,
                           gW + (size_t)(n0 + row) * KX + kb + seg * 8);
            }
        }
        CP_COMMIT();
    };

    stage(0);
    stage(1);
    for (int c = 0; c < 8; c++) {
        if (c < 7) CP_WAIT(1); else CP_WAIT(0);
        __syncthreads();
        const uint32_t sA = smem_base + (c % 3) * STAGEB;
        const uint32_t sB = sA + ABYTES;
#pragma unroll
        for (int ks = 0; ks < 4; ks++) {
            const int k16 = ks * 16;
            uint32_t bf[8][2];
#pragma unroll
            for (int nt2 = 0; nt2 < 4; nt2++) {
                uint32_t d0, d1, d2, d3;
                uint32_t addr = sB + (uint32_t)((nbase + nt2 * 16 + brow) * STR + k16 + bkh) * 2;
                LDSM_X4(d0, d1, d2, d3, addr);
                bf[nt2 * 2][0] = d0; bf[nt2 * 2][1] = d1;
                bf[nt2 * 2 + 1][0] = d2; bf[nt2 * 2 + 1][1] = d3;
            }
#pragma unroll
            for (int mt = 0; mt < 4; mt++) {
                uint32_t a0, a1, a2, a3;
                uint32_t addr = sA + (uint32_t)((mbase + mt * 16 + lrow) * STR + k16 + akh) * 2;
                LDSM_X4(a0, a1, a2, a3, addr);
#pragma unroll
                for (int nt = 0; nt < 8; nt++)
                    mma16816(acc[mt][nt], a0, a1, a2, a3, bf[nt][0], bf[nt][1]);
            }
        }
        if (c + 2 < 8) stage(c + 2);   // writes buffer (c+2)%3, disjoint from c%3 and (c+1)%3
    }

    // epilogue: write fp16 results
#pragma unroll
    for (int mt = 0; mt < 4; mt++) {
#pragma unroll
        for (int nt = 0; nt < 8; nt++) {
            int r = m0 + mbase + mt * 16 + (lane >> 2);
            int ccol = n0 + nbase + nt * 8 + (lane & 3) * 2;
            *(__half2*)(g_KV + (size_t)r * NOUT + ccol) =
                __floats2half2_rn(acc[mt][nt][0], acc[mt][nt][1]);
            *(__half2*)(g_KV + (size_t)(r + 8) * NOUT + ccol) =
                __floats2half2_rn(acc[mt][nt][2], acc[mt][nt][3]);
        }
    }
}

// ---------------- attention + MLP: 8 query nodes per CTA ----------------
// KV double-buffered in smem as fp16 via cp.async; warp-parallel softmax.
__global__ __launch_bounds__(256, 1)
void attn_kernel(int layer, const int* __restrict__ nghNode,
                 const int* __restrict__ srcA, const int* __restrict__ srcB,
                 const float* __restrict__ n_feat, const float* __restrict__ mem_tab,
                 const float* __restrict__ Wq, const float* __restrict__ Wm1,
                 const float* __restrict__ bm1, const float* __restrict__ Wm2,
                 const float* __restrict__ bm2) {
    extern __shared__ float sm[];
    __half* sKVh = (__half*)sm;              // 2 x 31040 halves = 31040 floats
    float* sSRC  = sm + 31040;               // 8*128
    float* sQ    = sm + 32064;               // 8*384
    float* sO    = sm + 35136;               // 8*384
    float* sS    = sm + 38208;               // 160
    float* sA1   = sm + 38368;               // 8*128
    int*   sMask = (int*)(sm + 39392);       // 40  (end 39432 floats)
    const int tid = threadIdx.x;
    const int nb = blockIdx.x;
    const uint32_t smem_base = smem_u32(sm);

    for (int i = tid; i < NPB * DF; i += 256) {
        int node = i >> 7, j = i & 127;
        int n = nb * NPB + node;
        int sid = (layer == 0) ? srcA[n] : ((n < BB) ? srcA[n] : srcB[n - BB]);
        sSRC[i] = n_feat[(size_t)sid * DF + j] + mem_tab[(size_t)sid * DF + j];
    }

    auto stageKV = [&](int i, int buf) {
        const __half* src = g_KV + (size_t)(nb * NPB + i) * KNB * NOUT;
        const uint32_t dbase = smem_base + buf * (KVBUFH * 2);
        for (int v = tid; v < KNB * 96; v += 256) {
            int row = v / 96, c8 = v % 96;
            CP_ASYNC16(dbase + (uint32_t)(row * KV2 + c8 * 8) * 2,
                       src + (size_t)row * NOUT + c8 * 8);
        }
        CP_COMMIT();
    };
    stageKV(0, 0);
    __syncthreads();

    // Q projection for all 8 nodes (weights loaded once, reused x8)
    {
        float acc0[NPB], acc1[NPB];
#pragma unroll
        for (int i = 0; i < NPB; i++) { acc0[i] = 0.f; acc1[i] = 0.f; }
        const float* wq = Wq + (size_t)layer * MDIM * MDIM;
        for (int m = 0; m < DF; m++) {
            float w0 = wq[(size_t)m * MDIM + tid];
            float w1 = (tid < 128) ? wq[(size_t)m * MDIM + 256 + tid] : 0.f;
#pragma unroll
            for (int i = 0; i < NPB; i++) {
                float x = sSRC[i * DF + m];
                acc0[i] = fmaf(x, w0, acc0[i]);
                acc1[i] = fmaf(x, w1, acc1[i]);
            }
        }
#pragma unroll
        for (int i = 0; i < NPB; i++) {
            sQ[i * MDIM + tid] = acc0[i] + g_qconst[layer][tid];
            if (tid < 128) sQ[i * MDIM + 256 + tid] = acc1[i] + g_qconst[layer][256 + tid];
        }
    }

    for (int i = 0; i < NPB; i++) {
        const int n = nb * NPB + i;
        if (i < 7) stageKV(i + 1, (i + 1) & 1);
        if (tid < KNB) sMask[tid] = (nghNode[n * KNB + tid] == 0) ? 1 : 0;
        if (i < 7) CP_WAIT(1); else CP_WAIT(0);
        __syncthreads();
        const __half* kvb = sKVh + (i & 1) * KVBUFH;
        // scores
        if (tid < HH * KNB) {
            int h = tid / KNB, row = tid % KNB;
            const __half2* kr2 = (const __half2*)(kvb + row * KV2 + h * DHD);
            const float* qk = sQ + i * MDIM + h * DHD;
            float s = 0.f;
#pragma unroll
            for (int d2 = 0; d2 < DHD / 2; d2++) {
                float2 kf = __half22float2(kr2[d2]);
                s = fmaf(qk[2 * d2], kf.x, s);
                s = fmaf(qk[2 * d2 + 1], kf.y, s);
            }
            s *= 0.10206207261596577f;   // 1/sqrt(96)
            if (sMask[row]) s = -1000000000.0f;
            sS[h * KNB + row] = s;
        }
        __syncthreads();
        // warp-parallel softmax: warp h handles head h
        if (tid < 128) {
            int h = tid >> 5, lane = tid & 31;
            float v0 = sS[h * KNB + lane];
            float v1 = (lane < 8) ? sS[h * KNB + 32 + lane] : -INFINITY;
            float mx = fmaxf(v0, v1);
#pragma unroll
            for (int o = 16; o > 0; o >>= 1)
                mx = fmaxf(mx, __shfl_xor_sync(0xFFFFFFFF, mx, o));
            float e0 = expf(v0 - mx);
            float e1 = (lane < 8) ? expf(v1 - mx) : 0.f;
            float sum = e0 + e1;
#pragma unroll
            for (int o = 16; o > 0; o >>= 1)
                sum += __shfl_xor_sync(0xFFFFFFFF, sum, o);
            float inv = 1.f / sum;
            sS[h * KNB + lane] = e0 * inv;
            if (lane < 8) sS[h * KNB + 32 + lane] = e1 * inv;
        }
        __syncthreads();
        // o = a @ V
        for (int cc = tid; cc < MDIM; cc += 256) {
            int h = cc / DHD;
            const float* a = sS + h * KNB;
            float o = 0.f;
            for (int k = 0; k < KNB; k++)
                o = fmaf(a[k], __half2float(kvb[k * KV2 + MDIM + cc]), o);
            sO[i * MDIM + cc] = o;
        }
        __syncthreads();
    }

    // MLP layer 1 (Wo folded into WoM1): 2 thread-halves x 4 nodes each
    {
        const int half = tid >> 7, col = tid & 127;
        float a[4];
#pragma unroll
        for (int i = 0; i < 4; i++) a[i] = bm1[layer * DF + col];
        const float* w1 = &g_WoM1[layer][col];
        for (int m = 0; m < MDIM; m++) {
            float w = w1[m * DF];
#pragma unroll
            for (int i = 0; i < 4; i++)
                a[i] = fmaf(sO[(half * 4 + i) * MDIM + m], w, a[i]);
        }
        const float* w1b = Wm1 + (size_t)(layer * 512 + MDIM) * DF + col;
        for (int m = 0; m < DF; m++) {
            float w = w1b[m * DF];
#pragma unroll
            for (int i = 0; i < 4; i++)
                a[i] = fmaf(sSRC[(half * 4 + i) * DF + m], w, a[i]);
        }
#pragma unroll
        for (int i = 0; i < 4; i++) sA1[(half * 4 + i) * DF + col] = fmaxf(a[i], 0.f);
    }
    __syncthreads();
    {
        const int half = tid >> 7, col = tid & 127;
        float a[4];
#pragma unroll
        for (int i = 0; i < 4; i++) a[i] = bm2[layer * DF + col];
        const float* w2 = Wm2 + (size_t)layer * DF * DF + col;
        for (int d = 0; d < DF; d++) {
            float w = w2[d * DF];
#pragma unroll
            for (int i = 0; i < 4; i++)
                a[i] = fmaf(sA1[(half * 4 + i) * DF + d], w, a[i]);
        }
        float* hout = (layer == 0) ? g_h1 : g_h2;
#pragma unroll
        for (int i = 0; i < 4; i++)
            hout[(size_t)(nb * NPB + half * 4 + i) * DF + col] = a[i];
    }
}

// ---------------- final bilinear score + sigmoid ----------------
__global__ void final_kernel(const int* __restrict__ etype_l,
                             const float* __restrict__ Wmatch,
                             const float* __restrict__ bmatch,
                             float* __restrict__ out) {
    __shared__ float ste[128];
    __shared__ float red[128];
    int b = blockIdx.x, d = threadIdx.x;
    int et = etype_l[b];
    ste[d] = g_h2[(BB + b) * DF + d];
    __syncthreads();
    float se = g_h2[b * DF + d];
    const float* wm = Wmatch + (size_t)(et * DF + d) * DF;
    float v = 0.f;
    for (int e = 0; e < DF; e++) v = fmaf(wm[e], ste[e], v);
    red[d] = se * v;
    __syncthreads();
    for (int s = 64; s > 0; s >>= 1) {
        if (d < s) red[d] += red[d + s];
        __syncthreads();
    }
    if (d == 0) {
        float score = red[0] + bmatch[et];
        out[b] = 1.f / (1.f + expf(-score));
    }
}

extern "C" void kernel_launch(void* const* d_in, const int* in_sizes, int n_in,
                              void* d_out, int out_size) {
    const int*   src_idx   = (const int*)d_in[0];
    const int*   tgt_idx   = (const int*)d_in[1];
    const float* cut_time  = (const float*)d_in[2];
    const int*   etype_l   = (const int*)d_in[5];
    const int*   ngh_node2 = (const int*)d_in[6];
    const int*   ngh_eidx2 = (const int*)d_in[7];
    const float* ngh_t2    = (const float*)d_in[8];
    const int*   ngh_et2   = (const int*)d_in[9];
    const int*   ngh_node1 = (const int*)d_in[11];
    const int*   ngh_eidx1 = (const int*)d_in[12];
    const float* ngh_t1    = (const float*)d_in[13];
    const int*   ngh_et1   = (const int*)d_in[14];
    const float* n_feat    = (const float*)d_in[16];
    const float* e_feat    = (const float*)d_in[17];
    const float* mem_tab   = (const float*)d_in[18];
    const float* freq      = (const float*)d_in[19];
    const float* phase     = (const float*)d_in[20];
    const float* Wq        = (const float*)d_in[21];
    const float* Wk        = (const float*)d_in[22];
    const float* Wv        = (const float*)d_in[23];
    const float* Wo        = (const float*)d_in[24];
    const float* Wm1       = (const float*)d_in[25];
    const float* bm1       = (const float*)d_in[26];
    const float* Wm2       = (const float*)d_in[27];
    const float* bm2       = (const float*)d_in[28];
    const float* Wrel      = (const float*)d_in[29];
    const float* Wmatch    = (const float*)d_in[30];
    const float* bmatch    = (const float*)d_in[31];
    float* out = (float*)d_out;

    const int GEMM_SMEM = 3 * STAGEB;            // 165888 B
    const int ATTN_SMEM = 39432 * 4;             // 157728 B
    cudaFuncSetAttribute(gemm_kernel, cudaFuncAttributeMaxDynamicSharedMemorySize, GEMM_SMEM);
    cudaFuncSetAttribute(attn_kernel, cudaFuncAttributeMaxDynamicSharedMemorySize, ATTN_SMEM);

    pre_weights<<<2 * NOUT, 128>>>(Wrel, Wk, Wv);
    pre_misc<<<770, 384>>>(Wq, Wo, Wm1, phase);

    // ---- layer 0: 10240 query nodes, 409600 neighbor rows ----
    gather_kernel<<<R1 / 4, 512>>>(0, ngh_node1, ngh_eidx1, ngh_t1, ngh_et1,
                                   ngh_t2, n_feat, mem_tab, e_feat, freq, phase);
    gemm_kernel<<<dim3(NOUT / 256, R1 / 128), 256, GEMM_SMEM>>>(0);
    attn_kernel<<<R2 / NPB, 256, ATTN_SMEM>>>(0, ngh_node1, ngh_node2, (const int*)0,
                                              n_feat, mem_tab, Wq, Wm1, bm1, Wm2, bm2);

    // ---- layer 1: 256 query nodes, 10240 neighbor rows ----
    gather_kernel<<<R2 / 4, 512>>>(1, ngh_node2, ngh_eidx2, ngh_t2, ngh_et2,
                                   cut_time, n_feat, mem_tab, e_feat, freq, phase);
    gemm_kernel<<<dim3(NOUT / 256, R2 / 128), 256, GEMM_SMEM>>>(1);
    attn_kernel<<<256 / NPB, 256, ATTN_SMEM>>>(1, ngh_node2, src_idx, tgt_idx,
                                               n_feat, mem_tab, Wq, Wm1, bm1, Wm2, bm2);

    final_kernel<<<BB, 128>>>(etype_l, Wmatch, bmatch, out);
}